// round 13
// baseline (speedup 1.0000x reference)
#include <cuda_runtime.h>
#include <cuda_fp16.h>
#include <cstdint>
#include <math.h>

// ---------------------------------------------------------------------------
// Problem constants
// ---------------------------------------------------------------------------
#define NB   256
#define TT   64
#define INW  150
#define INWP 160
#define HH   1024
#define G3   (3*HH)
#define H2   (2*HH)
#define NT   (NB*TT)
#define NCLS 60

// ---------------------------------------------------------------------------
// Device scratch
// ---------------------------------------------------------------------------
__device__ __half g_xn   [(size_t)NT * INWP];
__device__ __half g_wih0h[(size_t)2 * G3 * INWP];
__device__ __half g_wih1h[(size_t)2 * G3 * H2];
__device__ __half g_wih2h[(size_t)2 * G3 * H2];
__device__ __half g_whhh [3][(size_t)2 * G3 * HH];
__device__ float  g_gi   [2][(size_t)NT * G3];
__device__ __half g_bufAh[(size_t)NT * H2];
__device__ __half g_bufBh[(size_t)NT * H2];
__device__ float  g_h    [2][(size_t)NB * HH];
__device__ __half g_hh   [2][(size_t)NB * HH];
__device__ float  g_gh3  [3][2][(size_t)NB * G3];   // [kslice][dir]
__device__ float  g_bn   [2 * INW];
__device__ int          g_barc;
__device__ volatile int g_bars;

// ---------------------------------------------------------------------------
// PTX helpers
// ---------------------------------------------------------------------------
__device__ __forceinline__ void mma_f16(float* d,
                                        uint32_t a0, uint32_t a1, uint32_t a2, uint32_t a3,
                                        uint32_t b0, uint32_t b1)
{
    asm volatile(
        "mma.sync.aligned.m16n8k16.row.col.f32.f16.f16.f32 "
        "{%0,%1,%2,%3}, {%4,%5,%6,%7}, {%8,%9}, {%0,%1,%2,%3};"
        : "+f"(d[0]), "+f"(d[1]), "+f"(d[2]), "+f"(d[3])
        : "r"(a0), "r"(a1), "r"(a2), "r"(a3), "r"(b0), "r"(b1));
}

__device__ __forceinline__ void ldsm_x4(uint32_t* r, uint32_t addr)
{
    asm volatile("ldmatrix.sync.aligned.m8n8.x4.shared.b16 {%0,%1,%2,%3}, [%4];"
                 : "=r"(r[0]), "=r"(r[1]), "=r"(r[2]), "=r"(r[3]) : "r"(addr));
}

__device__ __forceinline__ uint32_t smem_u32(const void* p) {
    uint32_t a;
    asm("{ .reg .u64 t; cvta.to.shared.u64 t, %1; cvt.u32.u64 %0, t; }" : "=r"(a) : "l"(p));
    return a;
}

__device__ __forceinline__ void cp_async16(uint32_t saddr, const void* gaddr)
{
    asm volatile("cp.async.cg.shared.global [%0], [%1], 16;" :: "r"(saddr), "l"(gaddr));
}
#define CP_COMMIT() asm volatile("cp.async.commit_group;" ::: "memory")
#define CP_WAIT(n)  asm volatile("cp.async.wait_group %0;" :: "n"(n) : "memory")

// grid-wide sense-reversal barrier (all NBLK CTAs must be resident)
__device__ __forceinline__ void grid_bar(int nblk, int& sense)
{
    __threadfence();
    __syncthreads();
    if (threadIdx.x == 0) {
        sense ^= 1;
        if (atomicAdd(&g_barc, 1) == nblk - 1) {
            g_barc = 0;
            __threadfence();
            g_bars = sense;
        } else {
            while (g_bars != sense) __nanosleep(64);
        }
    }
    __syncthreads();
}

// ---------------------------------------------------------------------------
// Weight conversion fp32 -> fp16
// ---------------------------------------------------------------------------
__global__ void cvt_half_kernel(const float4* __restrict__ src, uint2* __restrict__ dst, size_t n4)
{
    for (size_t i = (size_t)blockIdx.x * blockDim.x + threadIdx.x; i < n4;
         i += (size_t)gridDim.x * blockDim.x) {
        float4 v = src[i];
        __half2 lo = __floats2half2_rn(v.x, v.y);
        __half2 hi = __floats2half2_rn(v.z, v.w);
        dst[i] = make_uint2(*(uint32_t*)&lo, *(uint32_t*)&hi);
    }
}

__global__ void cvt_wih0_kernel(const float* __restrict__ w)
{
    size_t i = (size_t)blockIdx.x * blockDim.x + threadIdx.x;
    if (i >= (size_t)2 * G3 * INWP) return;
    int c = (int)(i % INWP);
    size_t r = i / INWP;
    g_wih0h[i] = __float2half_rn((c < INW) ? w[r * INW + c] : 0.f);
}

// ---------------------------------------------------------------------------
// BatchNorm
// ---------------------------------------------------------------------------
__global__ void bn_stats_kernel(const float* __restrict__ x)
{
    int c = blockIdx.x;
    float s = 0.f, s2 = 0.f;
    for (int i = threadIdx.x; i < NT; i += blockDim.x) {
        float v = x[(size_t)i * INW + c];
        s += v; s2 += v * v;
    }
    __shared__ float sh0[256], sh1[256];
    sh0[threadIdx.x] = s; sh1[threadIdx.x] = s2;
    __syncthreads();
    for (int off = 128; off > 0; off >>= 1) {
        if (threadIdx.x < off) {
            sh0[threadIdx.x] += sh0[threadIdx.x + off];
            sh1[threadIdx.x] += sh1[threadIdx.x + off];
        }
        __syncthreads();
    }
    if (threadIdx.x == 0) {
        float mean = sh0[0] / (float)NT;
        float var  = sh1[0] / (float)NT - mean * mean;
        g_bn[c]       = mean;
        g_bn[INW + c] = rsqrtf(var + 1e-5f);
    }
}

__global__ void bn_apply_kernel(const float* __restrict__ x,
                                const float* __restrict__ gamma,
                                const float* __restrict__ beta)
{
    size_t i = (size_t)blockIdx.x * blockDim.x + threadIdx.x;
    if (i >= (size_t)NT * INWP) return;
    int c = (int)(i % INWP);
    size_t r = i / INWP;
    float v = 0.f;
    if (c < INW)
        v = (x[r * INW + c] - g_bn[c]) * g_bn[INW + c] * gamma[c] + beta[c];
    g_xn[i] = __float2half_rn(v);
}

// ---------------------------------------------------------------------------
// BIG input GEMM (unchanged from R10)
// ---------------------------------------------------------------------------
#define ROWB    80
#define BSTAGES 3
#define B_ROWS  (128 + 256)
#define B_STG   (B_ROWS * ROWB)
#define BGEMM_SMEM (BSTAGES * B_STG)

__global__ __launch_bounds__(256, 1)
void gemm_f16_big(const __half* __restrict__ A, const __half* __restrict__ B,
                  const float* __restrict__ bias, float* __restrict__ C,
                  int M, int N, int K,
                  long sAz, long sBz, long sbz, long sCz)
{
    extern __shared__ __align__(16) char smem[];
    const uint32_t s0 = smem_u32(smem);

    const int bz = blockIdx.z;
    A    += (long)bz * sAz;
    B    += (long)bz * sBz;
    bias += (long)bz * sbz;
    C    += (long)bz * sCz;

    const int n0 = blockIdx.x * 256;
    const int m0 = blockIdx.y * 128;
    const int tid  = threadIdx.x;
    const int warp = tid >> 5;
    const int lane = tid & 31;
    const int wm = warp & 1;
    const int wn = warp >> 1;

    const uint32_t aoff = (uint32_t)(wm * 64 + (lane & 7) + ((lane >> 3) & 1) * 8) * ROWB
                        + ((lane >> 4) & 1) * 16;
    const uint32_t boff = (uint32_t)(128 + wn * 64 + (lane & 7) + ((lane >> 4) & 1) * 8) * ROWB
                        + ((lane >> 3) & 1) * 16;

    const char* gptr[6];
    uint32_t    soff[6];
    #pragma unroll
    for (int c = 0; c < 6; c++) {
        const int chunk = c * 256 + tid;
        const int row  = chunk >> 2;
        const int part = chunk & 3;
        if (row < 128) {
            gptr[c] = (const char*)(A + (long)(m0 + row) * K) + part * 16;
            soff[c] = (uint32_t)row * ROWB + part * 16;
        } else {
            gptr[c] = (const char*)(B + (long)(n0 + row - 128) * K) + part * 16;
            soff[c] = (uint32_t)row * ROWB + part * 16;
        }
    }

    float acc[4][8][4];
    #pragma unroll
    for (int i = 0; i < 4; i++)
        #pragma unroll
        for (int j = 0; j < 8; j++)
            #pragma unroll
            for (int q = 0; q < 4; q++) acc[i][j][q] = 0.f;

    const int KT = K >> 5;

    #pragma unroll
    for (int p = 0; p < BSTAGES - 1; p++) {
        #pragma unroll
        for (int c = 0; c < 6; c++)
            cp_async16(s0 + p * B_STG + soff[c], gptr[c] + p * 64);
        CP_COMMIT();
    }

    for (int kt = 0; kt < KT; kt++) {
        if (kt < KT - 1) { CP_WAIT(1); } else { CP_WAIT(0); }
        __syncthreads();

        if (kt + BSTAGES - 1 < KT) {
            const int nt = kt + BSTAGES - 1;
            const uint32_t sbase = s0 + (nt % BSTAGES) * B_STG;
            #pragma unroll
            for (int c = 0; c < 6; c++)
                cp_async16(sbase + soff[c], gptr[c] + nt * 64);
            CP_COMMIT();
        }

        const uint32_t stg = s0 + (kt % BSTAGES) * B_STG;
        const uint32_t aBase = stg + aoff;
        const uint32_t bBase = stg + boff;

        #pragma unroll
        for (int s = 0; s < 2; s++) {
            uint32_t a[4][4], b[4][4];
            #pragma unroll
            for (int i = 0; i < 4; i++)
                ldsm_x4(a[i], aBase + i * 16 * ROWB + s * 32);
            #pragma unroll
            for (int j2 = 0; j2 < 4; j2++)
                ldsm_x4(b[j2], bBase + j2 * 16 * ROWB + s * 32);

            #pragma unroll
            for (int i = 0; i < 4; i++)
                #pragma unroll
                for (int j2 = 0; j2 < 4; j2++) {
                    mma_f16(acc[i][2 * j2],     a[i][0], a[i][1], a[i][2], a[i][3],
                            b[j2][0], b[j2][1]);
                    mma_f16(acc[i][2 * j2 + 1], a[i][0], a[i][1], a[i][2], a[i][3],
                            b[j2][2], b[j2][3]);
                }
        }
    }

    #pragma unroll
    for (int i = 0; i < 4; i++) {
        const int row = m0 + wm * 64 + i * 16 + (lane >> 2);
        #pragma unroll
        for (int j = 0; j < 8; j++) {
            const int col = n0 + wn * 64 + j * 8 + (lane & 3) * 2;
            const float bx = __ldg(&bias[col]);
            const float by = __ldg(&bias[col + 1]);
            *(float2*)&C[(long)row * N + col] =
                make_float2(acc[i][j][0] + bx, acc[i][j][1] + by);
            *(float2*)&C[(long)(row + 8) * N + col] =
                make_float2(acc[i][j][2] + bx, acc[i][j][3] + by);
        }
    }
}

// ---------------------------------------------------------------------------
// Persistent recurrent layer kernel: 64 timesteps in ONE launch.
// 288 CTAs (jobs = 24 x 2 x 6 of R10's split-K=3 grid), grid barrier
// between GEMM and gate phases. Gate phase reads cross-CTA partials
// via __ldcg (L2) to avoid stale L1.
// ---------------------------------------------------------------------------
#define STAGES 4
#define STAGEB (128 * ROWB)
#define GEMM_SMEM (STAGES * 2 * STAGEB)
#define NBLK   288
#define GATE_TOT (2 * NB * HH / 4)     // 131072 float4 elems

__global__ __launch_bounds__(256, 2)
void gru_layer_persist(const __half* __restrict__ Wh,   // [2][G3][HH]
                       const float* __restrict__ bhh,   // [2][G3]
                       __half* __restrict__ out_h, float* __restrict__ out_f)
{
    extern __shared__ __align__(16) char smem[];
    const uint32_t sA0 = smem_u32(smem);
    const uint32_t sB0 = sA0 + STAGES * STAGEB;

    // job decomposition
    const int bid = blockIdx.x;
    const int nx  = bid % 24;            // N tile
    const int rem = bid / 24;
    const int ny  = rem % 2;             // M tile
    const int z   = rem / 2;             // 0..5
    const int d   = z & 1;
    const int ks  = z >> 1;              // 0..2
    const int kt0 = ks * 11;
    const int KT  = (ks < 2) ? 11 : 10;

    const __half* A = g_hh[d];
    const __half* B = Wh + (size_t)d * G3 * HH;
    float* C = g_gh3[ks][d];

    const int n0 = nx * 128;
    const int m0 = ny * 128;
    const int tid  = threadIdx.x;
    const int warp = tid >> 5;
    const int lane = tid & 31;
    const int wm = warp & 1;
    const int wn = warp >> 1;

    const uint32_t aoff = (uint32_t)(wm * 64 + (lane & 7) + ((lane >> 3) & 1) * 8) * ROWB
                        + ((lane >> 4) & 1) * 16;
    const uint32_t boff = (uint32_t)(wn * 32 + (lane & 7) + ((lane >> 4) & 1) * 8) * ROWB
                        + ((lane >> 3) & 1) * 16;

    const int crow = tid >> 1;
    const int chal = tid & 1;
    const char* Ag = (const char*)(A + (long)(m0 + crow) * HH + kt0 * 32) + chal * 32;
    const char* Bg = (const char*)(B + (long)(n0 + crow) * HH + kt0 * 32) + chal * 32;
    const uint32_t sArow = sA0 + crow * ROWB + chal * 32;
    const uint32_t sBrow = sB0 + crow * ROWB + chal * 32;

    int sense = 0;
    const int gtid = bid * 256 + tid;

    for (int t = 0; t < TT; t++) {
        // ---------------- GEMM phase ----------------
        float acc[4][4][4];
        #pragma unroll
        for (int i = 0; i < 4; i++)
            #pragma unroll
            for (int j = 0; j < 4; j++)
                #pragma unroll
                for (int q = 0; q < 4; q++) acc[i][j][q] = 0.f;

        #pragma unroll
        for (int p = 0; p < STAGES - 1; p++) {
            const char* ag = Ag + p * 64;
            const char* bg = Bg + p * 64;
            const uint32_t sa = sArow + p * STAGEB;
            const uint32_t sb = sBrow + p * STAGEB;
            cp_async16(sa, ag);  cp_async16(sa + 16, ag + 16);
            cp_async16(sb, bg);  cp_async16(sb + 16, bg + 16);
            CP_COMMIT();
        }

        for (int kt = 0; kt < KT; kt++) {
            if      (kt <= KT - 3) { CP_WAIT(2); }
            else if (kt == KT - 2) { CP_WAIT(1); }
            else                   { CP_WAIT(0); }
            __syncthreads();

            if (kt + STAGES - 1 < KT) {
                const int nt = kt + STAGES - 1;
                const int sb_ = nt & 3;
                const char* ag = Ag + nt * 64;
                const char* bg = Bg + nt * 64;
                const uint32_t sa = sArow + sb_ * STAGEB;
                const uint32_t sbm = sBrow + sb_ * STAGEB;
                cp_async16(sa, ag);   cp_async16(sa + 16, ag + 16);
                cp_async16(sbm, bg);  cp_async16(sbm + 16, bg + 16);
                CP_COMMIT();
            }

            const int buf = kt & 3;
            const uint32_t aBase = sA0 + buf * STAGEB + aoff;
            const uint32_t bBase = sB0 + buf * STAGEB + boff;

            #pragma unroll
            for (int s = 0; s < 2; s++) {
                uint32_t a[4][4], b[2][4];
                #pragma unroll
                for (int i = 0; i < 4; i++)
                    ldsm_x4(a[i], aBase + i * 16 * ROWB + s * 32);
                #pragma unroll
                for (int j2 = 0; j2 < 2; j2++)
                    ldsm_x4(b[j2], bBase + j2 * 16 * ROWB + s * 32);

                #pragma unroll
                for (int i = 0; i < 4; i++)
                    #pragma unroll
                    for (int j2 = 0; j2 < 2; j2++) {
                        mma_f16(acc[i][2 * j2],     a[i][0], a[i][1], a[i][2], a[i][3],
                                b[j2][0], b[j2][1]);
                        mma_f16(acc[i][2 * j2 + 1], a[i][0], a[i][1], a[i][2], a[i][3],
                                b[j2][2], b[j2][3]);
                    }
            }
        }

        #pragma unroll
        for (int i = 0; i < 4; i++) {
            const int row = m0 + wm * 64 + i * 16 + (lane >> 2);
            #pragma unroll
            for (int j = 0; j < 4; j++) {
                const int col = n0 + wn * 32 + j * 8 + (lane & 3) * 2;
                *(float2*)&C[(long)row * G3 + col] =
                    make_float2(acc[i][j][0], acc[i][j][1]);
                *(float2*)&C[(long)(row + 8) * G3 + col] =
                    make_float2(acc[i][j][2], acc[i][j][3]);
            }
        }

        grid_bar(NBLK, sense);

        // ---------------- gate phase ----------------
        for (int idx = gtid; idx < GATE_TOT; idx += NBLK * 256) {
            const int dd  = idx >> 16;
            const int rm  = idx & 65535;
            const int n   = rm >> 8;
            const int jq  = rm & 255;

            const float4* gi = (const float4*)(g_gi[dd]     + (size_t)(n * TT + t) * G3);
            const float4* g0 = (const float4*)(g_gh3[0][dd] + (size_t)n * G3);
            const float4* g1 = (const float4*)(g_gh3[1][dd] + (size_t)n * G3);
            const float4* g2 = (const float4*)(g_gh3[2][dd] + (size_t)n * G3);
            const float4* bb = (const float4*)(bhh + (size_t)dd * G3);

            float4 ir = __ldg(&gi[jq]);
            float4 iz = __ldg(&gi[256 + jq]);
            float4 in = __ldg(&gi[512 + jq]);

            float4 hr, hz, hn;
            {
                float4 a0 = __ldcg(&g0[jq]), a1 = __ldcg(&g1[jq]), a2 = __ldcg(&g2[jq]);
                float4 bv = __ldg(&bb[jq]);
                hr = make_float4(a0.x + a1.x + a2.x + bv.x, a0.y + a1.y + a2.y + bv.y,
                                 a0.z + a1.z + a2.z + bv.z, a0.w + a1.w + a2.w + bv.w);
            }
            {
                float4 a0 = __ldcg(&g0[256 + jq]), a1 = __ldcg(&g1[256 + jq]), a2 = __ldcg(&g2[256 + jq]);
                float4 bv = __ldg(&bb[256 + jq]);
                hz = make_float4(a0.x + a1.x + a2.x + bv.x, a0.y + a1.y + a2.y + bv.y,
                                 a0.z + a1.z + a2.z + bv.z, a0.w + a1.w + a2.w + bv.w);
            }
            {
                float4 a0 = __ldcg(&g0[512 + jq]), a1 = __ldcg(&g1[512 + jq]), a2 = __ldcg(&g2[512 + jq]);
                float4 bv = __ldg(&bb[512 + jq]);
                hn = make_float4(a0.x + a1.x + a2.x + bv.x, a0.y + a1.y + a2.y + bv.y,
                                 a0.z + a1.z + a2.z + bv.z, a0.w + a1.w + a2.w + bv.w);
            }

            float4* hp = (float4*)(g_h[dd] + (size_t)n * HH) + jq;
            float4 ho = *hp;
            float4 hv;
            {
                float r = 1.f / (1.f + __expf(-(ir.x + hr.x)));
                float zz = 1.f / (1.f + __expf(-(iz.x + hz.x)));
                float nn = tanhf(in.x + r * hn.x);
                hv.x = (1.f - zz) * nn + zz * ho.x;
            }
            {
                float r = 1.f / (1.f + __expf(-(ir.y + hr.y)));
                float zz = 1.f / (1.f + __expf(-(iz.y + hz.y)));
                float nn = tanhf(in.y + r * hn.y);
                hv.y = (1.f - zz) * nn + zz * ho.y;
            }
            {
                float r = 1.f / (1.f + __expf(-(ir.z + hr.z)));
                float zz = 1.f / (1.f + __expf(-(iz.z + hz.z)));
                float nn = tanhf(in.z + r * hn.z);
                hv.z = (1.f - zz) * nn + zz * ho.z;
            }
            {
                float r = 1.f / (1.f + __expf(-(ir.w + hr.w)));
                float zz = 1.f / (1.f + __expf(-(iz.w + hz.w)));
                float nn = tanhf(in.w + r * hn.w);
                hv.w = (1.f - zz) * nn + zz * ho.w;
            }

            *hp = hv;

            __half2 h01 = __floats2half2_rn(hv.x, hv.y);
            __half2 h23 = __floats2half2_rn(hv.z, hv.w);
            __half2* hhp = (__half2*)(g_hh[dd] + (size_t)n * HH + 4 * jq);
            hhp[0] = h01; hhp[1] = h23;

            size_t ob = (size_t)(n * TT + t) * H2 + (size_t)dd * HH + 4 * jq;
            if (out_f) {
                *(float4*)(out_f + ob) = hv;
            } else {
                __half2* op = (__half2*)(out_h + ob);
                op[0] = h01; op[1] = h23;
            }
        }

        grid_bar(NBLK, sense);
    }
}

// ---------------------------------------------------------------------------
// hidden state + barrier zero
// ---------------------------------------------------------------------------
__global__ void hzero_kernel()
{
    size_t i = (size_t)blockIdx.x * blockDim.x + threadIdx.x;
    if (i < (size_t)2 * NB * HH) {
        ((float*)g_h)[i] = 0.f;
        ((__half*)g_hh)[i] = __float2half_rn(0.f);
    }
    if (i == 0) { g_barc = 0; g_bars = 0; }
}

// ---------------------------------------------------------------------------
// FC head
// ---------------------------------------------------------------------------
__global__ void fc_kernel(const float* __restrict__ enc,
                          const float* __restrict__ fc_w,
                          const float* __restrict__ fc_b,
                          float* __restrict__ out)
{
    int n = blockIdx.x;
    int c = threadIdx.x;
    if (c >= NCLS) return;
    const float* h = enc + ((size_t)n * TT + (TT - 1)) * H2;
    const float* w = fc_w + (size_t)c * H2;
    float s = 0.f;
    #pragma unroll 8
    for (int k = 0; k < H2; k++) s += h[k] * w[k];
    out[n * NCLS + c] = s + fc_b[c];
}

// ---------------------------------------------------------------------------
// Orchestration
// ---------------------------------------------------------------------------
extern "C" void kernel_launch(void* const* d_in, const int* in_sizes, int n_in,
                              void* d_out, int out_size)
{
    const float* x        = (const float*)d_in[0];
    const float* bn_gamma = (const float*)d_in[1];
    const float* bn_beta  = (const float*)d_in[2];
    const float* w_ih[3]  = {(const float*)d_in[3],  (const float*)d_in[7],  (const float*)d_in[11]};
    const float* w_hh[3]  = {(const float*)d_in[4],  (const float*)d_in[8],  (const float*)d_in[12]};
    const float* b_ih[3]  = {(const float*)d_in[5],  (const float*)d_in[9],  (const float*)d_in[13]};
    const float* b_hh[3]  = {(const float*)d_in[6],  (const float*)d_in[10], (const float*)d_in[14]};
    const float* fc_w     = (const float*)d_in[15];
    const float* fc_b     = (const float*)d_in[16];

    float* out = (float*)d_out;
    float* enc = out + (size_t)NB * NCLS;

    __half *p_xn, *p_wih0h, *p_wih1h, *p_wih2h, *p_whhh, *p_bufAh, *p_bufBh;
    cudaGetSymbolAddress((void**)&p_xn,    g_xn);
    cudaGetSymbolAddress((void**)&p_wih0h, g_wih0h);
    cudaGetSymbolAddress((void**)&p_wih1h, g_wih1h);
    cudaGetSymbolAddress((void**)&p_wih2h, g_wih2h);
    cudaGetSymbolAddress((void**)&p_whhh,  g_whhh);
    float* p_gi;
    cudaGetSymbolAddress((void**)&p_gi,    g_gi);
    cudaGetSymbolAddress((void**)&p_bufAh, g_bufAh);
    cudaGetSymbolAddress((void**)&p_bufBh, g_bufBh);

    static bool s_init = false;
    if (!s_init) {
        cudaFuncSetAttribute(gru_layer_persist, cudaFuncAttributeMaxDynamicSharedMemorySize, GEMM_SMEM);
        cudaFuncSetAttribute(gemm_f16_big, cudaFuncAttributeMaxDynamicSharedMemorySize, BGEMM_SMEM);
        s_init = true;
    }

    // ---- weight conversions ----
    {
        size_t n0 = (size_t)2 * G3 * INWP;
        cvt_wih0_kernel<<<(unsigned)((n0 + 255) / 256), 256>>>(w_ih[0]);
        size_t n1 = (size_t)2 * G3 * H2;
        cvt_half_kernel<<<1024, 256>>>((const float4*)w_ih[1], (uint2*)p_wih1h, n1 / 4);
        cvt_half_kernel<<<1024, 256>>>((const float4*)w_ih[2], (uint2*)p_wih2h, n1 / 4);
        size_t nh = (size_t)2 * G3 * HH;
        cvt_half_kernel<<<1024, 256>>>((const float4*)w_hh[0], (uint2*)(p_whhh + 0 * nh), nh / 4);
        cvt_half_kernel<<<1024, 256>>>((const float4*)w_hh[1], (uint2*)(p_whhh + 1 * nh), nh / 4);
        cvt_half_kernel<<<1024, 256>>>((const float4*)w_hh[2], (uint2*)(p_whhh + 2 * nh), nh / 4);
    }

    // ---- BatchNorm ----
    bn_stats_kernel<<<INW, 256>>>(x);
    {
        size_t n = (size_t)NT * INWP;
        bn_apply_kernel<<<(unsigned)((n + 255) / 256), 256>>>(x, bn_gamma, bn_beta);
    }

    const __half* layer_in[3]   = {p_xn, p_bufAh, p_bufBh};
    __half*       layer_outh[3] = {p_bufAh, p_bufBh, nullptr};
    float*        layer_outf[3] = {nullptr, nullptr, enc};
    const int     layer_k[3]    = {INWP, H2, H2};
    const __half* layer_wih[3]  = {p_wih0h, p_wih1h, p_wih2h};
    const size_t  nh = (size_t)2 * G3 * HH;

    for (int l = 0; l < 3; l++) {
        const int K = layer_k[l];

        // gi[d] = X @ w_ih[l][d]^T + b_ih[l][d]
        {
            dim3 grid(G3 / 256, NT / 128, 2);
            gemm_f16_big<<<grid, 256, BGEMM_SMEM>>>(layer_in[l], layer_wih[l], b_ih[l], p_gi,
                                                    NT, G3, K,
                                                    0L, (long)G3 * K, (long)G3, (long)NT * G3);
        }

        hzero_kernel<<<(2 * NB * HH) / 256, 256>>>();

        // entire 64-step recurrence in one persistent launch
        gru_layer_persist<<<NBLK, 256, GEMM_SMEM>>>(p_whhh + (size_t)l * nh, b_hh[l],
                                                    layer_outh[l], layer_outf[l]);
    }

    fc_kernel<<<NB, 64>>>(enc, fc_w, fc_b, out);
}

// round 14
// speedup vs baseline: 1.0327x; 1.0327x over previous
#include <cuda_runtime.h>
#include <cuda_fp16.h>
#include <cstdint>
#include <math.h>

// ---------------------------------------------------------------------------
// Problem constants
// ---------------------------------------------------------------------------
#define NB   256
#define TT   64
#define INW  150
#define INWP 160
#define HH   1024
#define G3   (3*HH)
#define H2   (2*HH)
#define NT   (NB*TT)
#define NCLS 60

// ---------------------------------------------------------------------------
// Device scratch
// ---------------------------------------------------------------------------
__device__ __half g_xn   [(size_t)NT * INWP];
__device__ __half g_wih0h[(size_t)2 * G3 * INWP];
__device__ __half g_wih1h[(size_t)2 * G3 * H2];
__device__ __half g_wih2h[(size_t)2 * G3 * H2];
__device__ __half g_whhh [3][(size_t)2 * G3 * HH];
__device__ __half g_gi   [2][(size_t)NT * G3];      // fp16 input preactivations
__device__ __half g_bufAh[(size_t)NT * H2];
__device__ __half g_bufBh[(size_t)NT * H2];
__device__ float  g_h    [2][(size_t)NB * HH];
__device__ __half g_hh   [2][(size_t)NB * HH];
__device__ __half g_gh3  [3][2][(size_t)NB * G3];   // fp16 split-K partials
__device__ float  g_bn   [2 * INW];

// ---------------------------------------------------------------------------
// PTX helpers
// ---------------------------------------------------------------------------
__device__ __forceinline__ void mma_f16(float* d,
                                        uint32_t a0, uint32_t a1, uint32_t a2, uint32_t a3,
                                        uint32_t b0, uint32_t b1)
{
    asm volatile(
        "mma.sync.aligned.m16n8k16.row.col.f32.f16.f16.f32 "
        "{%0,%1,%2,%3}, {%4,%5,%6,%7}, {%8,%9}, {%0,%1,%2,%3};"
        : "+f"(d[0]), "+f"(d[1]), "+f"(d[2]), "+f"(d[3])
        : "r"(a0), "r"(a1), "r"(a2), "r"(a3), "r"(b0), "r"(b1));
}

__device__ __forceinline__ void ldsm_x4(uint32_t* r, uint32_t addr)
{
    asm volatile("ldmatrix.sync.aligned.m8n8.x4.shared.b16 {%0,%1,%2,%3}, [%4];"
                 : "=r"(r[0]), "=r"(r[1]), "=r"(r[2]), "=r"(r[3]) : "r"(addr));
}

__device__ __forceinline__ uint32_t smem_u32(const void* p) {
    uint32_t a;
    asm("{ .reg .u64 t; cvta.to.shared.u64 t, %1; cvt.u32.u64 %0, t; }" : "=r"(a) : "l"(p));
    return a;
}

__device__ __forceinline__ void cp_async16(uint32_t saddr, const void* gaddr)
{
    asm volatile("cp.async.cg.shared.global [%0], [%1], 16;" :: "r"(saddr), "l"(gaddr));
}
#define CP_COMMIT() asm volatile("cp.async.commit_group;" ::: "memory")
#define CP_WAIT(n)  asm volatile("cp.async.wait_group %0;" :: "n"(n) : "memory")

// half4 (uint2) -> float4
__device__ __forceinline__ float4 h4f4(uint2 v)
{
    __half2 lo = *(__half2*)&v.x;
    __half2 hi = *(__half2*)&v.y;
    float2 a = __half22float2(lo);
    float2 b = __half22float2(hi);
    return make_float4(a.x, a.y, b.x, b.y);
}

// ---------------------------------------------------------------------------
// Weight conversion fp32 -> fp16
// ---------------------------------------------------------------------------
__global__ void cvt_half_kernel(const float4* __restrict__ src, uint2* __restrict__ dst, size_t n4)
{
    for (size_t i = (size_t)blockIdx.x * blockDim.x + threadIdx.x; i < n4;
         i += (size_t)gridDim.x * blockDim.x) {
        float4 v = src[i];
        __half2 lo = __floats2half2_rn(v.x, v.y);
        __half2 hi = __floats2half2_rn(v.z, v.w);
        dst[i] = make_uint2(*(uint32_t*)&lo, *(uint32_t*)&hi);
    }
}

__global__ void cvt_wih0_kernel(const float* __restrict__ w)
{
    size_t i = (size_t)blockIdx.x * blockDim.x + threadIdx.x;
    if (i >= (size_t)2 * G3 * INWP) return;
    int c = (int)(i % INWP);
    size_t r = i / INWP;
    g_wih0h[i] = __float2half_rn((c < INW) ? w[r * INW + c] : 0.f);
}

// ---------------------------------------------------------------------------
// BatchNorm
// ---------------------------------------------------------------------------
__global__ void bn_stats_kernel(const float* __restrict__ x)
{
    int c = blockIdx.x;
    float s = 0.f, s2 = 0.f;
    for (int i = threadIdx.x; i < NT; i += blockDim.x) {
        float v = x[(size_t)i * INW + c];
        s += v; s2 += v * v;
    }
    __shared__ float sh0[256], sh1[256];
    sh0[threadIdx.x] = s; sh1[threadIdx.x] = s2;
    __syncthreads();
    for (int off = 128; off > 0; off >>= 1) {
        if (threadIdx.x < off) {
            sh0[threadIdx.x] += sh0[threadIdx.x + off];
            sh1[threadIdx.x] += sh1[threadIdx.x + off];
        }
        __syncthreads();
    }
    if (threadIdx.x == 0) {
        float mean = sh0[0] / (float)NT;
        float var  = sh1[0] / (float)NT - mean * mean;
        g_bn[c]       = mean;
        g_bn[INW + c] = rsqrtf(var + 1e-5f);
    }
}

__global__ void bn_apply_kernel(const float* __restrict__ x,
                                const float* __restrict__ gamma,
                                const float* __restrict__ beta)
{
    size_t i = (size_t)blockIdx.x * blockDim.x + threadIdx.x;
    if (i >= (size_t)NT * INWP) return;
    int c = (int)(i % INWP);
    size_t r = i / INWP;
    float v = 0.f;
    if (c < INW)
        v = (x[r * INW + c] - g_bn[c]) * g_bn[INW + c] * gamma[c] + beta[c];
    g_xn[i] = __float2half_rn(v);
}

// ---------------------------------------------------------------------------
// BIG input GEMM:  C[M,N] = half(A[M,K]*B[N,K]^T + bias[N])   (fp32 accum)
// CTA 128x256x32, 8 warps, warp tile 64x64, 3-stage cp.async, ldmatrix.
// ---------------------------------------------------------------------------
#define ROWB    80
#define BSTAGES 3
#define B_ROWS  (128 + 256)
#define B_STG   (B_ROWS * ROWB)
#define BGEMM_SMEM (BSTAGES * B_STG)

__global__ __launch_bounds__(256, 1)
void gemm_f16_big(const __half* __restrict__ A, const __half* __restrict__ B,
                  const float* __restrict__ bias, __half* __restrict__ C,
                  int M, int N, int K,
                  long sAz, long sBz, long sbz, long sCz)
{
    extern __shared__ __align__(16) char smem[];
    const uint32_t s0 = smem_u32(smem);

    const int bz = blockIdx.z;
    A    += (long)bz * sAz;
    B    += (long)bz * sBz;
    bias += (long)bz * sbz;
    C    += (long)bz * sCz;

    const int n0 = blockIdx.x * 256;
    const int m0 = blockIdx.y * 128;
    const int tid  = threadIdx.x;
    const int warp = tid >> 5;
    const int lane = tid & 31;
    const int wm = warp & 1;
    const int wn = warp >> 1;

    const uint32_t aoff = (uint32_t)(wm * 64 + (lane & 7) + ((lane >> 3) & 1) * 8) * ROWB
                        + ((lane >> 4) & 1) * 16;
    const uint32_t boff = (uint32_t)(128 + wn * 64 + (lane & 7) + ((lane >> 4) & 1) * 8) * ROWB
                        + ((lane >> 3) & 1) * 16;

    const char* gptr[6];
    uint32_t    soff[6];
    #pragma unroll
    for (int c = 0; c < 6; c++) {
        const int chunk = c * 256 + tid;
        const int row  = chunk >> 2;
        const int part = chunk & 3;
        if (row < 128) {
            gptr[c] = (const char*)(A + (long)(m0 + row) * K) + part * 16;
            soff[c] = (uint32_t)row * ROWB + part * 16;
        } else {
            gptr[c] = (const char*)(B + (long)(n0 + row - 128) * K) + part * 16;
            soff[c] = (uint32_t)row * ROWB + part * 16;
        }
    }

    float acc[4][8][4];
    #pragma unroll
    for (int i = 0; i < 4; i++)
        #pragma unroll
        for (int j = 0; j < 8; j++)
            #pragma unroll
            for (int q = 0; q < 4; q++) acc[i][j][q] = 0.f;

    const int KT = K >> 5;

    #pragma unroll
    for (int p = 0; p < BSTAGES - 1; p++) {
        #pragma unroll
        for (int c = 0; c < 6; c++)
            cp_async16(s0 + p * B_STG + soff[c], gptr[c] + p * 64);
        CP_COMMIT();
    }

    for (int kt = 0; kt < KT; kt++) {
        if (kt < KT - 1) { CP_WAIT(1); } else { CP_WAIT(0); }
        __syncthreads();

        if (kt + BSTAGES - 1 < KT) {
            const int nt = kt + BSTAGES - 1;
            const uint32_t sbase = s0 + (nt % BSTAGES) * B_STG;
            #pragma unroll
            for (int c = 0; c < 6; c++)
                cp_async16(sbase + soff[c], gptr[c] + nt * 64);
            CP_COMMIT();
        }

        const uint32_t stg = s0 + (kt % BSTAGES) * B_STG;
        const uint32_t aBase = stg + aoff;
        const uint32_t bBase = stg + boff;

        #pragma unroll
        for (int s = 0; s < 2; s++) {
            uint32_t a[4][4], b[4][4];
            #pragma unroll
            for (int i = 0; i < 4; i++)
                ldsm_x4(a[i], aBase + i * 16 * ROWB + s * 32);
            #pragma unroll
            for (int j2 = 0; j2 < 4; j2++)
                ldsm_x4(b[j2], bBase + j2 * 16 * ROWB + s * 32);

            #pragma unroll
            for (int i = 0; i < 4; i++)
                #pragma unroll
                for (int j2 = 0; j2 < 4; j2++) {
                    mma_f16(acc[i][2 * j2],     a[i][0], a[i][1], a[i][2], a[i][3],
                            b[j2][0], b[j2][1]);
                    mma_f16(acc[i][2 * j2 + 1], a[i][0], a[i][1], a[i][2], a[i][3],
                            b[j2][2], b[j2][3]);
                }
        }
    }

    #pragma unroll
    for (int i = 0; i < 4; i++) {
        const int row = m0 + wm * 64 + i * 16 + (lane >> 2);
        #pragma unroll
        for (int j = 0; j < 8; j++) {
            const int col = n0 + wn * 64 + j * 8 + (lane & 3) * 2;
            const float bx = __ldg(&bias[col]);
            const float by = __ldg(&bias[col + 1]);
            __half2 v0 = __floats2half2_rn(acc[i][j][0] + bx, acc[i][j][1] + by);
            __half2 v1 = __floats2half2_rn(acc[i][j][2] + bx, acc[i][j][3] + by);
            *(uint32_t*)&C[(long)row * N + col]       = *(uint32_t*)&v0;
            *(uint32_t*)&C[(long)(row + 8) * N + col] = *(uint32_t*)&v1;
        }
    }
}

// ---------------------------------------------------------------------------
// Recurrent GEMM, split-K=3 (288 CTAs), fp16 partial outputs.
// ---------------------------------------------------------------------------
#define STAGES 4
#define STAGEB (128 * ROWB)
#define GEMM_SMEM (STAGES * 2 * STAGEB)

__global__ __launch_bounds__(256, 2)
void gemm_f16_rec(const __half* __restrict__ Wh)   // layer base [2][G3][HH]
{
    extern __shared__ __align__(16) char smem[];
    const uint32_t sA0 = smem_u32(smem);
    const uint32_t sB0 = sA0 + STAGES * STAGEB;

    const int d  = blockIdx.z & 1;
    const int ks = blockIdx.z >> 1;           // 0,1,2
    const int kt0 = ks * 11;
    const int KT  = (ks < 2) ? 11 : 10;

    const __half* A = g_hh[d];
    const __half* B = Wh + (size_t)d * G3 * HH;
    __half* C = g_gh3[ks][d];

    const int n0 = blockIdx.x * 128;
    const int m0 = blockIdx.y * 128;
    const int tid  = threadIdx.x;
    const int warp = tid >> 5;
    const int lane = tid & 31;
    const int wm = warp & 1;
    const int wn = warp >> 1;

    const uint32_t aoff = (uint32_t)(wm * 64 + (lane & 7) + ((lane >> 3) & 1) * 8) * ROWB
                        + ((lane >> 4) & 1) * 16;
    const uint32_t boff = (uint32_t)(wn * 32 + (lane & 7) + ((lane >> 4) & 1) * 8) * ROWB
                        + ((lane >> 3) & 1) * 16;

    const int crow = tid >> 1;
    const int chal = tid & 1;
    const char* Ag = (const char*)(A + (long)(m0 + crow) * HH + kt0 * 32) + chal * 32;
    const char* Bg = (const char*)(B + (long)(n0 + crow) * HH + kt0 * 32) + chal * 32;
    const uint32_t sArow = sA0 + crow * ROWB + chal * 32;
    const uint32_t sBrow = sB0 + crow * ROWB + chal * 32;

    float acc[4][4][4];
    #pragma unroll
    for (int i = 0; i < 4; i++)
        #pragma unroll
        for (int j = 0; j < 4; j++)
            #pragma unroll
            for (int q = 0; q < 4; q++) acc[i][j][q] = 0.f;

    #pragma unroll
    for (int p = 0; p < STAGES - 1; p++) {
        const char* ag = Ag + p * 64;
        const char* bg = Bg + p * 64;
        const uint32_t sa = sArow + p * STAGEB;
        const uint32_t sb = sBrow + p * STAGEB;
        cp_async16(sa, ag);  cp_async16(sa + 16, ag + 16);
        cp_async16(sb, bg);  cp_async16(sb + 16, bg + 16);
        CP_COMMIT();
    }

    for (int kt = 0; kt < KT; kt++) {
        if      (kt <= KT - 3) { CP_WAIT(2); }
        else if (kt == KT - 2) { CP_WAIT(1); }
        else                   { CP_WAIT(0); }
        __syncthreads();

        if (kt + STAGES - 1 < KT) {
            const int nt = kt + STAGES - 1;
            const int sb_ = nt & 3;
            const char* ag = Ag + nt * 64;
            const char* bg = Bg + nt * 64;
            const uint32_t sa = sArow + sb_ * STAGEB;
            const uint32_t sbm = sBrow + sb_ * STAGEB;
            cp_async16(sa, ag);   cp_async16(sa + 16, ag + 16);
            cp_async16(sbm, bg);  cp_async16(sbm + 16, bg + 16);
            CP_COMMIT();
        }

        const int buf = kt & 3;
        const uint32_t aBase = sA0 + buf * STAGEB + aoff;
        const uint32_t bBase = sB0 + buf * STAGEB + boff;

        #pragma unroll
        for (int s = 0; s < 2; s++) {
            uint32_t a[4][4], b[2][4];
            #pragma unroll
            for (int i = 0; i < 4; i++)
                ldsm_x4(a[i], aBase + i * 16 * ROWB + s * 32);
            #pragma unroll
            for (int j2 = 0; j2 < 2; j2++)
                ldsm_x4(b[j2], bBase + j2 * 16 * ROWB + s * 32);

            #pragma unroll
            for (int i = 0; i < 4; i++)
                #pragma unroll
                for (int j2 = 0; j2 < 2; j2++) {
                    mma_f16(acc[i][2 * j2],     a[i][0], a[i][1], a[i][2], a[i][3],
                            b[j2][0], b[j2][1]);
                    mma_f16(acc[i][2 * j2 + 1], a[i][0], a[i][1], a[i][2], a[i][3],
                            b[j2][2], b[j2][3]);
                }
        }
    }

    #pragma unroll
    for (int i = 0; i < 4; i++) {
        const int row = m0 + wm * 64 + i * 16 + (lane >> 2);
        #pragma unroll
        for (int j = 0; j < 4; j++) {
            const int col = n0 + wn * 32 + j * 8 + (lane & 3) * 2;
            __half2 v0 = __floats2half2_rn(acc[i][j][0], acc[i][j][1]);
            __half2 v1 = __floats2half2_rn(acc[i][j][2], acc[i][j][3]);
            *(uint32_t*)&C[(long)row * G3 + col]       = *(uint32_t*)&v0;
            *(uint32_t*)&C[(long)(row + 8) * G3 + col] = *(uint32_t*)&v1;
        }
    }
}

// ---------------------------------------------------------------------------
// hidden state zero
// ---------------------------------------------------------------------------
__global__ void hzero_kernel()
{
    size_t i = (size_t)blockIdx.x * blockDim.x + threadIdx.x;
    if (i < (size_t)2 * NB * HH) {
        ((float*)g_h)[i] = 0.f;
        ((__half*)g_hh)[i] = __float2half_rn(0.f);
    }
}

// ---------------------------------------------------------------------------
// GRU gate elementwise: gh = f32(gh3[0]) + f32(gh3[1]) + f32(gh3[2]) + b_hh
// All math fp32; gi/partials fp16 transport.
// ---------------------------------------------------------------------------
__global__ __launch_bounds__(256)
void gru_gate_kernel(__half* __restrict__ out_h, float* __restrict__ out_f,
                     const float* __restrict__ bhh, int t)
{
    int idx = blockIdx.x * blockDim.x + threadIdx.x;
    if (idx >= 2 * NB * HH / 4) return;
    int d   = idx >> 16;
    int rem = idx & 65535;
    int n   = rem >> 8;
    int jq  = rem & 255;       // half4 group within 1024 units

    const uint2* gi = (const uint2*)(g_gi[d]     + (size_t)(n * TT + t) * G3);
    const uint2* g0 = (const uint2*)(g_gh3[0][d] + (size_t)n * G3);
    const uint2* g1 = (const uint2*)(g_gh3[1][d] + (size_t)n * G3);
    const uint2* g2 = (const uint2*)(g_gh3[2][d] + (size_t)n * G3);
    const float4* bb = (const float4*)(bhh + (size_t)d * G3);

    float4 ir = h4f4(__ldg(&gi[jq]));
    float4 iz = h4f4(__ldg(&gi[256 + jq]));
    float4 in = h4f4(__ldg(&gi[512 + jq]));

    float4 hr, hz, hn;
    {
        float4 a0 = h4f4(__ldg(&g0[jq])), a1 = h4f4(__ldg(&g1[jq])), a2 = h4f4(__ldg(&g2[jq]));
        float4 bv = __ldg(&bb[jq]);
        hr = make_float4(a0.x + a1.x + a2.x + bv.x, a0.y + a1.y + a2.y + bv.y,
                         a0.z + a1.z + a2.z + bv.z, a0.w + a1.w + a2.w + bv.w);
    }
    {
        float4 a0 = h4f4(__ldg(&g0[256 + jq])), a1 = h4f4(__ldg(&g1[256 + jq])), a2 = h4f4(__ldg(&g2[256 + jq]));
        float4 bv = __ldg(&bb[256 + jq]);
        hz = make_float4(a0.x + a1.x + a2.x + bv.x, a0.y + a1.y + a2.y + bv.y,
                         a0.z + a1.z + a2.z + bv.z, a0.w + a1.w + a2.w + bv.w);
    }
    {
        float4 a0 = h4f4(__ldg(&g0[512 + jq])), a1 = h4f4(__ldg(&g1[512 + jq])), a2 = h4f4(__ldg(&g2[512 + jq]));
        float4 bv = __ldg(&bb[512 + jq]);
        hn = make_float4(a0.x + a1.x + a2.x + bv.x, a0.y + a1.y + a2.y + bv.y,
                         a0.z + a1.z + a2.z + bv.z, a0.w + a1.w + a2.w + bv.w);
    }

    float4* hp = (float4*)(g_h[d] + (size_t)n * HH) + jq;
    float4 ho = *hp;
    float4 hv;

    {
        float r = 1.f / (1.f + __expf(-(ir.x + hr.x)));
        float z = 1.f / (1.f + __expf(-(iz.x + hz.x)));
        float nn = tanhf(in.x + r * hn.x);
        hv.x = (1.f - z) * nn + z * ho.x;
    }
    {
        float r = 1.f / (1.f + __expf(-(ir.y + hr.y)));
        float z = 1.f / (1.f + __expf(-(iz.y + hz.y)));
        float nn = tanhf(in.y + r * hn.y);
        hv.y = (1.f - z) * nn + z * ho.y;
    }
    {
        float r = 1.f / (1.f + __expf(-(ir.z + hr.z)));
        float z = 1.f / (1.f + __expf(-(iz.z + hz.z)));
        float nn = tanhf(in.z + r * hn.z);
        hv.z = (1.f - z) * nn + z * ho.z;
    }
    {
        float r = 1.f / (1.f + __expf(-(ir.w + hr.w)));
        float z = 1.f / (1.f + __expf(-(iz.w + hz.w)));
        float nn = tanhf(in.w + r * hn.w);
        hv.w = (1.f - z) * nn + z * ho.w;
    }

    *hp = hv;

    __half2 h01 = __floats2half2_rn(hv.x, hv.y);
    __half2 h23 = __floats2half2_rn(hv.z, hv.w);
    __half2* hhp = (__half2*)(g_hh[d] + (size_t)n * HH + 4 * jq);
    hhp[0] = h01; hhp[1] = h23;

    size_t ob = (size_t)(n * TT + t) * H2 + (size_t)d * HH + 4 * jq;
    if (out_f) {
        *(float4*)(out_f + ob) = hv;
    } else {
        __half2* op = (__half2*)(out_h + ob);
        op[0] = h01; op[1] = h23;
    }
}

// ---------------------------------------------------------------------------
// FC head
// ---------------------------------------------------------------------------
__global__ void fc_kernel(const float* __restrict__ enc,
                          const float* __restrict__ fc_w,
                          const float* __restrict__ fc_b,
                          float* __restrict__ out)
{
    int n = blockIdx.x;
    int c = threadIdx.x;
    if (c >= NCLS) return;
    const float* h = enc + ((size_t)n * TT + (TT - 1)) * H2;
    const float* w = fc_w + (size_t)c * H2;
    float s = 0.f;
    #pragma unroll 8
    for (int k = 0; k < H2; k++) s += h[k] * w[k];
    out[n * NCLS + c] = s + fc_b[c];
}

// ---------------------------------------------------------------------------
// Orchestration (identical topology to R10)
// ---------------------------------------------------------------------------
extern "C" void kernel_launch(void* const* d_in, const int* in_sizes, int n_in,
                              void* d_out, int out_size)
{
    const float* x        = (const float*)d_in[0];
    const float* bn_gamma = (const float*)d_in[1];
    const float* bn_beta  = (const float*)d_in[2];
    const float* w_ih[3]  = {(const float*)d_in[3],  (const float*)d_in[7],  (const float*)d_in[11]};
    const float* w_hh[3]  = {(const float*)d_in[4],  (const float*)d_in[8],  (const float*)d_in[12]};
    const float* b_ih[3]  = {(const float*)d_in[5],  (const float*)d_in[9],  (const float*)d_in[13]};
    const float* b_hh[3]  = {(const float*)d_in[6],  (const float*)d_in[10], (const float*)d_in[14]};
    const float* fc_w     = (const float*)d_in[15];
    const float* fc_b     = (const float*)d_in[16];

    float* out = (float*)d_out;
    float* enc = out + (size_t)NB * NCLS;

    __half *p_xn, *p_wih0h, *p_wih1h, *p_wih2h, *p_whhh, *p_bufAh, *p_bufBh, *p_gi;
    cudaGetSymbolAddress((void**)&p_xn,    g_xn);
    cudaGetSymbolAddress((void**)&p_wih0h, g_wih0h);
    cudaGetSymbolAddress((void**)&p_wih1h, g_wih1h);
    cudaGetSymbolAddress((void**)&p_wih2h, g_wih2h);
    cudaGetSymbolAddress((void**)&p_whhh,  g_whhh);
    cudaGetSymbolAddress((void**)&p_gi,    g_gi);
    cudaGetSymbolAddress((void**)&p_bufAh, g_bufAh);
    cudaGetSymbolAddress((void**)&p_bufBh, g_bufBh);

    static bool s_init = false;
    if (!s_init) {
        cudaFuncSetAttribute(gemm_f16_rec, cudaFuncAttributeMaxDynamicSharedMemorySize, GEMM_SMEM);
        cudaFuncSetAttribute(gemm_f16_big, cudaFuncAttributeMaxDynamicSharedMemorySize, BGEMM_SMEM);
        s_init = true;
    }

    // ---- weight conversions ----
    {
        size_t n0 = (size_t)2 * G3 * INWP;
        cvt_wih0_kernel<<<(unsigned)((n0 + 255) / 256), 256>>>(w_ih[0]);
        size_t n1 = (size_t)2 * G3 * H2;
        cvt_half_kernel<<<1024, 256>>>((const float4*)w_ih[1], (uint2*)p_wih1h, n1 / 4);
        cvt_half_kernel<<<1024, 256>>>((const float4*)w_ih[2], (uint2*)p_wih2h, n1 / 4);
        size_t nh = (size_t)2 * G3 * HH;
        cvt_half_kernel<<<1024, 256>>>((const float4*)w_hh[0], (uint2*)(p_whhh + 0 * nh), nh / 4);
        cvt_half_kernel<<<1024, 256>>>((const float4*)w_hh[1], (uint2*)(p_whhh + 1 * nh), nh / 4);
        cvt_half_kernel<<<1024, 256>>>((const float4*)w_hh[2], (uint2*)(p_whhh + 2 * nh), nh / 4);
    }

    // ---- BatchNorm ----
    bn_stats_kernel<<<INW, 256>>>(x);
    {
        size_t n = (size_t)NT * INWP;
        bn_apply_kernel<<<(unsigned)((n + 255) / 256), 256>>>(x, bn_gamma, bn_beta);
    }

    const __half* layer_in[3]   = {p_xn, p_bufAh, p_bufBh};
    __half*       layer_outh[3] = {p_bufAh, p_bufBh, nullptr};
    float*        layer_outf[3] = {nullptr, nullptr, enc};
    const int     layer_k[3]    = {INWP, H2, H2};
    const __half* layer_wih[3]  = {p_wih0h, p_wih1h, p_wih2h};
    const size_t  nh = (size_t)2 * G3 * HH;

    for (int l = 0; l < 3; l++) {
        const int K = layer_k[l];

        // gi[d] = half(X @ w_ih[l][d]^T + b_ih[l][d])
        {
            dim3 grid(G3 / 256, NT / 128, 2);
            gemm_f16_big<<<grid, 256, BGEMM_SMEM>>>(layer_in[l], layer_wih[l], b_ih[l], p_gi,
                                                    NT, G3, K,
                                                    0L, (long)G3 * K, (long)G3, (long)NT * G3);
        }

        hzero_kernel<<<(2 * NB * HH) / 256, 256>>>();

        for (int t = 0; t < TT; t++) {
            dim3 grid(G3 / 128, NB / 128, 6);   // z: d + 2*kslice
            gemm_f16_rec<<<grid, 256, GEMM_SMEM>>>(p_whhh + (size_t)l * nh);
            gru_gate_kernel<<<512, 256>>>(layer_outh[l], layer_outf[l], b_hh[l], t);
        }
    }

    fc_kernel<<<NB, 64>>>(enc, fc_w, fc_b, out);
}

// round 15
// speedup vs baseline: 1.0721x; 1.0382x over previous
#include <cuda_runtime.h>
#include <cuda_fp16.h>
#include <cstdint>
#include <math.h>

// ---------------------------------------------------------------------------
// Problem constants
// ---------------------------------------------------------------------------
#define NB   256
#define TT   64
#define INW  150
#define INWP 160
#define HH   1024
#define G3   (3*HH)
#define H2   (2*HH)
#define NT   (NB*TT)
#define NCLS 60

// ---------------------------------------------------------------------------
// Device scratch
// ---------------------------------------------------------------------------
__device__ __half g_xn   [(size_t)NT * INWP];
__device__ __half g_wih0h[(size_t)2 * G3 * INWP];
__device__ __half g_wih1h[(size_t)2 * G3 * H2];
__device__ __half g_wih2h[(size_t)2 * G3 * H2];
__device__ __half g_whhh [3][(size_t)2 * G3 * HH];
__device__ __half g_gi   [2][(size_t)NT * G3];      // fp16 input preactivations
__device__ __half g_bufAh[(size_t)NT * H2];
__device__ __half g_bufBh[(size_t)NT * H2];
__device__ float  g_h    [2][(size_t)NB * HH];
__device__ __half g_hh   [2][(size_t)NB * HH];
__device__ __half g_gh3  [3][2][(size_t)NB * G3];   // fp16 split-K partials
__device__ float  g_bn   [2 * INW];

// ---------------------------------------------------------------------------
// PTX helpers
// ---------------------------------------------------------------------------
__device__ __forceinline__ void mma_f16(float* d,
                                        uint32_t a0, uint32_t a1, uint32_t a2, uint32_t a3,
                                        uint32_t b0, uint32_t b1)
{
    asm volatile(
        "mma.sync.aligned.m16n8k16.row.col.f32.f16.f16.f32 "
        "{%0,%1,%2,%3}, {%4,%5,%6,%7}, {%8,%9}, {%0,%1,%2,%3};"
        : "+f"(d[0]), "+f"(d[1]), "+f"(d[2]), "+f"(d[3])
        : "r"(a0), "r"(a1), "r"(a2), "r"(a3), "r"(b0), "r"(b1));
}

__device__ __forceinline__ void ldsm_x4(uint32_t* r, uint32_t addr)
{
    asm volatile("ldmatrix.sync.aligned.m8n8.x4.shared.b16 {%0,%1,%2,%3}, [%4];"
                 : "=r"(r[0]), "=r"(r[1]), "=r"(r[2]), "=r"(r[3]) : "r"(addr));
}

__device__ __forceinline__ uint32_t smem_u32(const void* p) {
    uint32_t a;
    asm("{ .reg .u64 t; cvta.to.shared.u64 t, %1; cvt.u32.u64 %0, t; }" : "=r"(a) : "l"(p));
    return a;
}

__device__ __forceinline__ void cp_async16(uint32_t saddr, const void* gaddr)
{
    asm volatile("cp.async.cg.shared.global [%0], [%1], 16;" :: "r"(saddr), "l"(gaddr));
}
#define CP_COMMIT() asm volatile("cp.async.commit_group;" ::: "memory")
#define CP_WAIT(n)  asm volatile("cp.async.wait_group %0;" :: "n"(n) : "memory")

// half4 (uint2) -> float4
__device__ __forceinline__ float4 h4f4(uint2 v)
{
    __half2 lo = *(__half2*)&v.x;
    __half2 hi = *(__half2*)&v.y;
    float2 a = __half22float2(lo);
    float2 b = __half22float2(hi);
    return make_float4(a.x, a.y, b.x, b.y);
}

// ---------------------------------------------------------------------------
// Weight conversion fp32 -> fp16
// ---------------------------------------------------------------------------
__global__ void cvt_half_kernel(const float4* __restrict__ src, uint2* __restrict__ dst, size_t n4)
{
    for (size_t i = (size_t)blockIdx.x * blockDim.x + threadIdx.x; i < n4;
         i += (size_t)gridDim.x * blockDim.x) {
        float4 v = src[i];
        __half2 lo = __floats2half2_rn(v.x, v.y);
        __half2 hi = __floats2half2_rn(v.z, v.w);
        dst[i] = make_uint2(*(uint32_t*)&lo, *(uint32_t*)&hi);
    }
}

__global__ void cvt_wih0_kernel(const float* __restrict__ w)
{
    size_t i = (size_t)blockIdx.x * blockDim.x + threadIdx.x;
    if (i >= (size_t)2 * G3 * INWP) return;
    int c = (int)(i % INWP);
    size_t r = i / INWP;
    g_wih0h[i] = __float2half_rn((c < INW) ? w[r * INW + c] : 0.f);
}

// ---------------------------------------------------------------------------
// BatchNorm
// ---------------------------------------------------------------------------
__global__ void bn_stats_kernel(const float* __restrict__ x)
{
    int c = blockIdx.x;
    float s = 0.f, s2 = 0.f;
    for (int i = threadIdx.x; i < NT; i += blockDim.x) {
        float v = x[(size_t)i * INW + c];
        s += v; s2 += v * v;
    }
    __shared__ float sh0[256], sh1[256];
    sh0[threadIdx.x] = s; sh1[threadIdx.x] = s2;
    __syncthreads();
    for (int off = 128; off > 0; off >>= 1) {
        if (threadIdx.x < off) {
            sh0[threadIdx.x] += sh0[threadIdx.x + off];
            sh1[threadIdx.x] += sh1[threadIdx.x + off];
        }
        __syncthreads();
    }
    if (threadIdx.x == 0) {
        float mean = sh0[0] / (float)NT;
        float var  = sh1[0] / (float)NT - mean * mean;
        g_bn[c]       = mean;
        g_bn[INW + c] = rsqrtf(var + 1e-5f);
    }
}

__global__ void bn_apply_kernel(const float* __restrict__ x,
                                const float* __restrict__ gamma,
                                const float* __restrict__ beta)
{
    size_t i = (size_t)blockIdx.x * blockDim.x + threadIdx.x;
    if (i >= (size_t)NT * INWP) return;
    int c = (int)(i % INWP);
    size_t r = i / INWP;
    float v = 0.f;
    if (c < INW)
        v = (x[r * INW + c] - g_bn[c]) * g_bn[INW + c] * gamma[c] + beta[c];
    g_xn[i] = __float2half_rn(v);
}

// ---------------------------------------------------------------------------
// BIG input GEMM:  C[M,N] = half(A[M,K]*B[N,K]^T + bias[N])   (fp32 accum)
// CTA 128x256x32, 8 warps, warp tile 64x64, 3-stage cp.async, ldmatrix.
// ---------------------------------------------------------------------------
#define ROWB    80
#define BSTAGES 3
#define B_ROWS  (128 + 256)
#define B_STG   (B_ROWS * ROWB)
#define BGEMM_SMEM (BSTAGES * B_STG)

__global__ __launch_bounds__(256, 1)
void gemm_f16_big(const __half* __restrict__ A, const __half* __restrict__ B,
                  const float* __restrict__ bias, __half* __restrict__ C,
                  int M, int N, int K,
                  long sAz, long sBz, long sbz, long sCz)
{
    extern __shared__ __align__(16) char smem[];
    const uint32_t s0 = smem_u32(smem);

    const int bz = blockIdx.z;
    A    += (long)bz * sAz;
    B    += (long)bz * sBz;
    bias += (long)bz * sbz;
    C    += (long)bz * sCz;

    const int n0 = blockIdx.x * 256;
    const int m0 = blockIdx.y * 128;
    const int tid  = threadIdx.x;
    const int warp = tid >> 5;
    const int lane = tid & 31;
    const int wm = warp & 1;
    const int wn = warp >> 1;

    const uint32_t aoff = (uint32_t)(wm * 64 + (lane & 7) + ((lane >> 3) & 1) * 8) * ROWB
                        + ((lane >> 4) & 1) * 16;
    const uint32_t boff = (uint32_t)(128 + wn * 64 + (lane & 7) + ((lane >> 4) & 1) * 8) * ROWB
                        + ((lane >> 3) & 1) * 16;

    const char* gptr[6];
    uint32_t    soff[6];
    #pragma unroll
    for (int c = 0; c < 6; c++) {
        const int chunk = c * 256 + tid;
        const int row  = chunk >> 2;
        const int part = chunk & 3;
        if (row < 128) {
            gptr[c] = (const char*)(A + (long)(m0 + row) * K) + part * 16;
            soff[c] = (uint32_t)row * ROWB + part * 16;
        } else {
            gptr[c] = (const char*)(B + (long)(n0 + row - 128) * K) + part * 16;
            soff[c] = (uint32_t)row * ROWB + part * 16;
        }
    }

    float acc[4][8][4];
    #pragma unroll
    for (int i = 0; i < 4; i++)
        #pragma unroll
        for (int j = 0; j < 8; j++)
            #pragma unroll
            for (int q = 0; q < 4; q++) acc[i][j][q] = 0.f;

    const int KT = K >> 5;

    #pragma unroll
    for (int p = 0; p < BSTAGES - 1; p++) {
        #pragma unroll
        for (int c = 0; c < 6; c++)
            cp_async16(s0 + p * B_STG + soff[c], gptr[c] + p * 64);
        CP_COMMIT();
    }

    for (int kt = 0; kt < KT; kt++) {
        if (kt < KT - 1) { CP_WAIT(1); } else { CP_WAIT(0); }
        __syncthreads();

        if (kt + BSTAGES - 1 < KT) {
            const int nt = kt + BSTAGES - 1;
            const uint32_t sbase = s0 + (nt % BSTAGES) * B_STG;
            #pragma unroll
            for (int c = 0; c < 6; c++)
                cp_async16(sbase + soff[c], gptr[c] + nt * 64);
            CP_COMMIT();
        }

        const uint32_t stg = s0 + (kt % BSTAGES) * B_STG;
        const uint32_t aBase = stg + aoff;
        const uint32_t bBase = stg + boff;

        #pragma unroll
        for (int s = 0; s < 2; s++) {
            uint32_t a[4][4], b[4][4];
            #pragma unroll
            for (int i = 0; i < 4; i++)
                ldsm_x4(a[i], aBase + i * 16 * ROWB + s * 32);
            #pragma unroll
            for (int j2 = 0; j2 < 4; j2++)
                ldsm_x4(b[j2], bBase + j2 * 16 * ROWB + s * 32);

            #pragma unroll
            for (int i = 0; i < 4; i++)
                #pragma unroll
                for (int j2 = 0; j2 < 4; j2++) {
                    mma_f16(acc[i][2 * j2],     a[i][0], a[i][1], a[i][2], a[i][3],
                            b[j2][0], b[j2][1]);
                    mma_f16(acc[i][2 * j2 + 1], a[i][0], a[i][1], a[i][2], a[i][3],
                            b[j2][2], b[j2][3]);
                }
        }
    }

    #pragma unroll
    for (int i = 0; i < 4; i++) {
        const int row = m0 + wm * 64 + i * 16 + (lane >> 2);
        #pragma unroll
        for (int j = 0; j < 8; j++) {
            const int col = n0 + wn * 64 + j * 8 + (lane & 3) * 2;
            const float bx = __ldg(&bias[col]);
            const float by = __ldg(&bias[col + 1]);
            __half2 v0 = __floats2half2_rn(acc[i][j][0] + bx, acc[i][j][1] + by);
            __half2 v1 = __floats2half2_rn(acc[i][j][2] + bx, acc[i][j][3] + by);
            *(uint32_t*)&C[(long)row * N + col]       = *(uint32_t*)&v0;
            *(uint32_t*)&C[(long)(row + 8) * N + col] = *(uint32_t*)&v1;
        }
    }
}

// ---------------------------------------------------------------------------
// Recurrent GEMM, split-K=3, FAT tiles: CTA 128x256, warp 64x64.
// Grid (12, 2, 6) = 144 CTAs -> exactly one wave at occupancy 1.
//   gh3[ks][d] = half(h[d][:, slice] @ Wh[d]^T)   slices 352/352/320
// ---------------------------------------------------------------------------
__global__ __launch_bounds__(256, 1)
void gemm_f16_rec(const __half* __restrict__ Wh)   // layer base [2][G3][HH]
{
    extern __shared__ __align__(16) char smem[];
    const uint32_t s0 = smem_u32(smem);

    const int d  = blockIdx.z & 1;
    const int ks = blockIdx.z >> 1;           // 0,1,2
    const int kt0 = ks * 11;
    const int KT  = (ks < 2) ? 11 : 10;

    const __half* A = g_hh[d];                     // [NB][HH]
    const __half* B = Wh + (size_t)d * G3 * HH;    // [G3][HH]
    __half* C = g_gh3[ks][d];                      // [NB][G3]

    const int n0 = blockIdx.x * 256;
    const int m0 = blockIdx.y * 128;
    const int tid  = threadIdx.x;
    const int warp = tid >> 5;
    const int lane = tid & 31;
    const int wm = warp & 1;
    const int wn = warp >> 1;

    const uint32_t aoff = (uint32_t)(wm * 64 + (lane & 7) + ((lane >> 3) & 1) * 8) * ROWB
                        + ((lane >> 4) & 1) * 16;
    const uint32_t boff = (uint32_t)(128 + wn * 64 + (lane & 7) + ((lane >> 4) & 1) * 8) * ROWB
                        + ((lane >> 3) & 1) * 16;

    const char* gptr[6];
    uint32_t    soff[6];
    #pragma unroll
    for (int c = 0; c < 6; c++) {
        const int chunk = c * 256 + tid;
        const int row  = chunk >> 2;
        const int part = chunk & 3;
        if (row < 128) {
            gptr[c] = (const char*)(A + (long)(m0 + row) * HH + kt0 * 32) + part * 16;
            soff[c] = (uint32_t)row * ROWB + part * 16;
        } else {
            gptr[c] = (const char*)(B + (long)(n0 + row - 128) * HH + kt0 * 32) + part * 16;
            soff[c] = (uint32_t)row * ROWB + part * 16;
        }
    }

    float acc[4][8][4];
    #pragma unroll
    for (int i = 0; i < 4; i++)
        #pragma unroll
        for (int j = 0; j < 8; j++)
            #pragma unroll
            for (int q = 0; q < 4; q++) acc[i][j][q] = 0.f;

    #pragma unroll
    for (int p = 0; p < BSTAGES - 1; p++) {
        #pragma unroll
        for (int c = 0; c < 6; c++)
            cp_async16(s0 + p * B_STG + soff[c], gptr[c] + p * 64);
        CP_COMMIT();
    }

    for (int kt = 0; kt < KT; kt++) {
        if (kt < KT - 1) { CP_WAIT(1); } else { CP_WAIT(0); }
        __syncthreads();

        if (kt + BSTAGES - 1 < KT) {
            const int nt = kt + BSTAGES - 1;
            const uint32_t sbase = s0 + (nt % BSTAGES) * B_STG;
            #pragma unroll
            for (int c = 0; c < 6; c++)
                cp_async16(sbase + soff[c], gptr[c] + nt * 64);
            CP_COMMIT();
        }

        const uint32_t stg = s0 + (kt % BSTAGES) * B_STG;
        const uint32_t aBase = stg + aoff;
        const uint32_t bBase = stg + boff;

        #pragma unroll
        for (int s = 0; s < 2; s++) {
            uint32_t a[4][4], b[4][4];
            #pragma unroll
            for (int i = 0; i < 4; i++)
                ldsm_x4(a[i], aBase + i * 16 * ROWB + s * 32);
            #pragma unroll
            for (int j2 = 0; j2 < 4; j2++)
                ldsm_x4(b[j2], bBase + j2 * 16 * ROWB + s * 32);

            #pragma unroll
            for (int i = 0; i < 4; i++)
                #pragma unroll
                for (int j2 = 0; j2 < 4; j2++) {
                    mma_f16(acc[i][2 * j2],     a[i][0], a[i][1], a[i][2], a[i][3],
                            b[j2][0], b[j2][1]);
                    mma_f16(acc[i][2 * j2 + 1], a[i][0], a[i][1], a[i][2], a[i][3],
                            b[j2][2], b[j2][3]);
                }
        }
    }

    #pragma unroll
    for (int i = 0; i < 4; i++) {
        const int row = m0 + wm * 64 + i * 16 + (lane >> 2);
        #pragma unroll
        for (int j = 0; j < 8; j++) {
            const int col = n0 + wn * 64 + j * 8 + (lane & 3) * 2;
            __half2 v0 = __floats2half2_rn(acc[i][j][0], acc[i][j][1]);
            __half2 v1 = __floats2half2_rn(acc[i][j][2], acc[i][j][3]);
            *(uint32_t*)&C[(long)row * G3 + col]       = *(uint32_t*)&v0;
            *(uint32_t*)&C[(long)(row + 8) * G3 + col] = *(uint32_t*)&v1;
        }
    }
}

// ---------------------------------------------------------------------------
// hidden state zero
// ---------------------------------------------------------------------------
__global__ void hzero_kernel()
{
    size_t i = (size_t)blockIdx.x * blockDim.x + threadIdx.x;
    if (i < (size_t)2 * NB * HH) {
        ((float*)g_h)[i] = 0.f;
        ((__half*)g_hh)[i] = __float2half_rn(0.f);
    }
}

// ---------------------------------------------------------------------------
// GRU gate elementwise: gh = f32(gh3[0]) + f32(gh3[1]) + f32(gh3[2]) + b_hh
// ---------------------------------------------------------------------------
__global__ __launch_bounds__(256)
void gru_gate_kernel(__half* __restrict__ out_h, float* __restrict__ out_f,
                     const float* __restrict__ bhh, int t)
{
    int idx = blockIdx.x * blockDim.x + threadIdx.x;
    if (idx >= 2 * NB * HH / 4) return;
    int d   = idx >> 16;
    int rem = idx & 65535;
    int n   = rem >> 8;
    int jq  = rem & 255;

    const uint2* gi = (const uint2*)(g_gi[d]     + (size_t)(n * TT + t) * G3);
    const uint2* g0 = (const uint2*)(g_gh3[0][d] + (size_t)n * G3);
    const uint2* g1 = (const uint2*)(g_gh3[1][d] + (size_t)n * G3);
    const uint2* g2 = (const uint2*)(g_gh3[2][d] + (size_t)n * G3);
    const float4* bb = (const float4*)(bhh + (size_t)d * G3);

    float4 ir = h4f4(__ldg(&gi[jq]));
    float4 iz = h4f4(__ldg(&gi[256 + jq]));
    float4 in = h4f4(__ldg(&gi[512 + jq]));

    float4 hr, hz, hn;
    {
        float4 a0 = h4f4(__ldg(&g0[jq])), a1 = h4f4(__ldg(&g1[jq])), a2 = h4f4(__ldg(&g2[jq]));
        float4 bv = __ldg(&bb[jq]);
        hr = make_float4(a0.x + a1.x + a2.x + bv.x, a0.y + a1.y + a2.y + bv.y,
                         a0.z + a1.z + a2.z + bv.z, a0.w + a1.w + a2.w + bv.w);
    }
    {
        float4 a0 = h4f4(__ldg(&g0[256 + jq])), a1 = h4f4(__ldg(&g1[256 + jq])), a2 = h4f4(__ldg(&g2[256 + jq]));
        float4 bv = __ldg(&bb[256 + jq]);
        hz = make_float4(a0.x + a1.x + a2.x + bv.x, a0.y + a1.y + a2.y + bv.y,
                         a0.z + a1.z + a2.z + bv.z, a0.w + a1.w + a2.w + bv.w);
    }
    {
        float4 a0 = h4f4(__ldg(&g0[512 + jq])), a1 = h4f4(__ldg(&g1[512 + jq])), a2 = h4f4(__ldg(&g2[512 + jq]));
        float4 bv = __ldg(&bb[512 + jq]);
        hn = make_float4(a0.x + a1.x + a2.x + bv.x, a0.y + a1.y + a2.y + bv.y,
                         a0.z + a1.z + a2.z + bv.z, a0.w + a1.w + a2.w + bv.w);
    }

    float4* hp = (float4*)(g_h[d] + (size_t)n * HH) + jq;
    float4 ho = *hp;
    float4 hv;

    {
        float r = 1.f / (1.f + __expf(-(ir.x + hr.x)));
        float z = 1.f / (1.f + __expf(-(iz.x + hz.x)));
        float nn = tanhf(in.x + r * hn.x);
        hv.x = (1.f - z) * nn + z * ho.x;
    }
    {
        float r = 1.f / (1.f + __expf(-(ir.y + hr.y)));
        float z = 1.f / (1.f + __expf(-(iz.y + hz.y)));
        float nn = tanhf(in.y + r * hn.y);
        hv.y = (1.f - z) * nn + z * ho.y;
    }
    {
        float r = 1.f / (1.f + __expf(-(ir.z + hr.z)));
        float z = 1.f / (1.f + __expf(-(iz.z + hz.z)));
        float nn = tanhf(in.z + r * hn.z);
        hv.z = (1.f - z) * nn + z * ho.z;
    }
    {
        float r = 1.f / (1.f + __expf(-(ir.w + hr.w)));
        float z = 1.f / (1.f + __expf(-(iz.w + hz.w)));
        float nn = tanhf(in.w + r * hn.w);
        hv.w = (1.f - z) * nn + z * ho.w;
    }

    *hp = hv;

    __half2 h01 = __floats2half2_rn(hv.x, hv.y);
    __half2 h23 = __floats2half2_rn(hv.z, hv.w);
    __half2* hhp = (__half2*)(g_hh[d] + (size_t)n * HH + 4 * jq);
    hhp[0] = h01; hhp[1] = h23;

    size_t ob = (size_t)(n * TT + t) * H2 + (size_t)d * HH + 4 * jq;
    if (out_f) {
        *(float4*)(out_f + ob) = hv;
    } else {
        __half2* op = (__half2*)(out_h + ob);
        op[0] = h01; op[1] = h23;
    }
}

// ---------------------------------------------------------------------------
// FC head
// ---------------------------------------------------------------------------
__global__ void fc_kernel(const float* __restrict__ enc,
                          const float* __restrict__ fc_w,
                          const float* __restrict__ fc_b,
                          float* __restrict__ out)
{
    int n = blockIdx.x;
    int c = threadIdx.x;
    if (c >= NCLS) return;
    const float* h = enc + ((size_t)n * TT + (TT - 1)) * H2;
    const float* w = fc_w + (size_t)c * H2;
    float s = 0.f;
    #pragma unroll 8
    for (int k = 0; k < H2; k++) s += h[k] * w[k];
    out[n * NCLS + c] = s + fc_b[c];
}

// ---------------------------------------------------------------------------
// Orchestration
// ---------------------------------------------------------------------------
extern "C" void kernel_launch(void* const* d_in, const int* in_sizes, int n_in,
                              void* d_out, int out_size)
{
    const float* x        = (const float*)d_in[0];
    const float* bn_gamma = (const float*)d_in[1];
    const float* bn_beta  = (const float*)d_in[2];
    const float* w_ih[3]  = {(const float*)d_in[3],  (const float*)d_in[7],  (const float*)d_in[11]};
    const float* w_hh[3]  = {(const float*)d_in[4],  (const float*)d_in[8],  (const float*)d_in[12]};
    const float* b_ih[3]  = {(const float*)d_in[5],  (const float*)d_in[9],  (const float*)d_in[13]};
    const float* b_hh[3]  = {(const float*)d_in[6],  (const float*)d_in[10], (const float*)d_in[14]};
    const float* fc_w     = (const float*)d_in[15];
    const float* fc_b     = (const float*)d_in[16];

    float* out = (float*)d_out;
    float* enc = out + (size_t)NB * NCLS;

    __half *p_xn, *p_wih0h, *p_wih1h, *p_wih2h, *p_whhh, *p_bufAh, *p_bufBh, *p_gi;
    cudaGetSymbolAddress((void**)&p_xn,    g_xn);
    cudaGetSymbolAddress((void**)&p_wih0h, g_wih0h);
    cudaGetSymbolAddress((void**)&p_wih1h, g_wih1h);
    cudaGetSymbolAddress((void**)&p_wih2h, g_wih2h);
    cudaGetSymbolAddress((void**)&p_whhh,  g_whhh);
    cudaGetSymbolAddress((void**)&p_gi,    g_gi);
    cudaGetSymbolAddress((void**)&p_bufAh, g_bufAh);
    cudaGetSymbolAddress((void**)&p_bufBh, g_bufBh);

    static bool s_init = false;
    if (!s_init) {
        cudaFuncSetAttribute(gemm_f16_rec, cudaFuncAttributeMaxDynamicSharedMemorySize, BGEMM_SMEM);
        cudaFuncSetAttribute(gemm_f16_big, cudaFuncAttributeMaxDynamicSharedMemorySize, BGEMM_SMEM);
        s_init = true;
    }

    // ---- weight conversions ----
    {
        size_t n0 = (size_t)2 * G3 * INWP;
        cvt_wih0_kernel<<<(unsigned)((n0 + 255) / 256), 256>>>(w_ih[0]);
        size_t n1 = (size_t)2 * G3 * H2;
        cvt_half_kernel<<<1024, 256>>>((const float4*)w_ih[1], (uint2*)p_wih1h, n1 / 4);
        cvt_half_kernel<<<1024, 256>>>((const float4*)w_ih[2], (uint2*)p_wih2h, n1 / 4);
        size_t nh = (size_t)2 * G3 * HH;
        cvt_half_kernel<<<1024, 256>>>((const float4*)w_hh[0], (uint2*)(p_whhh + 0 * nh), nh / 4);
        cvt_half_kernel<<<1024, 256>>>((const float4*)w_hh[1], (uint2*)(p_whhh + 1 * nh), nh / 4);
        cvt_half_kernel<<<1024, 256>>>((const float4*)w_hh[2], (uint2*)(p_whhh + 2 * nh), nh / 4);
    }

    // ---- BatchNorm ----
    bn_stats_kernel<<<INW, 256>>>(x);
    {
        size_t n = (size_t)NT * INWP;
        bn_apply_kernel<<<(unsigned)((n + 255) / 256), 256>>>(x, bn_gamma, bn_beta);
    }

    const __half* layer_in[3]   = {p_xn, p_bufAh, p_bufBh};
    __half*       layer_outh[3] = {p_bufAh, p_bufBh, nullptr};
    float*        layer_outf[3] = {nullptr, nullptr, enc};
    const int     layer_k[3]    = {INWP, H2, H2};
    const __half* layer_wih[3]  = {p_wih0h, p_wih1h, p_wih2h};
    const size_t  nh = (size_t)2 * G3 * HH;

    for (int l = 0; l < 3; l++) {
        const int K = layer_k[l];

        // gi[d] = half(X @ w_ih[l][d]^T + b_ih[l][d])
        {
            dim3 grid(G3 / 256, NT / 128, 2);
            gemm_f16_big<<<grid, 256, BGEMM_SMEM>>>(layer_in[l], layer_wih[l], b_ih[l], p_gi,
                                                    NT, G3, K,
                                                    0L, (long)G3 * K, (long)G3, (long)NT * G3);
        }

        hzero_kernel<<<(2 * NB * HH) / 256, 256>>>();

        for (int t = 0; t < TT; t++) {
            dim3 grid(G3 / 256, NB / 128, 6);   // 144 CTAs: z = d + 2*kslice
            gemm_f16_rec<<<grid, 256, BGEMM_SMEM>>>(p_whhh + (size_t)l * nh);
            gru_gate_kernel<<<512, 256>>>(layer_outh[l], layer_outf[l], b_hh[l], t);
        }
    }

    fc_kernel<<<NB, 64>>>(enc, fc_w, fc_b, out);
}